// round 16
// baseline (speedup 1.0000x reference)
#include <cuda_runtime.h>
#include <cuda_bf16.h>

#define B_SZ    8
#define T_SZ    2048
#define VOCAB   8192
#define NT      256                  // 8 warps per CTA
#define SPLIT   16                   // CTAs (vocab slices) per batch row
#define SLICE   (VOCAB / SPLIT)      // 512 vocab entries per CTA
#define TPT     8                    // tokens per thread

__global__ __launch_bounds__(NT)
void constrained_attn_kernel(const int* __restrict__ x,
                             const float* __restrict__ params,
                             float* __restrict__ out)
{
    __shared__ float vslice[SLICE];    // 2 KB — this CTA's vocab slice
    __shared__ float zcorr;            // sparse softmax-Z correction

    const int b     = blockIdx.x >> 4;      // batch row
    const int slice = blockIdx.x & 15;      // vocab slice id
    const int tid   = threadIdx.x;

    const int* xb = x + b * T_SZ;

    // init smem (covered by BAR 1): 2 floats per thread
    vslice[tid]      = 0.0f;
    vslice[tid + NT] = 0.0f;
    if (tid == 0) zcorr = 0.0f;

    // ---- tokens: thread owns t0 = 8*tid .. 8*tid+7 (two int4 loads) ----
    const int4 w0 = reinterpret_cast<const int4*>(xb)[2 * tid];
    const int4 w1 = reinterpret_cast<const int4*>(xb)[2 * tid + 1];
    // neighbors toks[t0-2], toks[t0-1]: int2 at element offset 8*tid-2 (8B aligned)
    const int2 prev = (tid > 0)
        ? *reinterpret_cast<const int2*>(xb + 8 * tid - 2)
        : make_int2(-1, -1);                                     // sentinels

    // keys window: k[j] = toks[t0 - 2 + j], j = 0..9
    int k[TPT + 2];
    k[0] = prev.x; k[1] = prev.y;
    k[2] = w0.x; k[3] = w0.y; k[4] = w0.z; k[5] = w0.w;
    k[6] = w1.x; k[7] = w1.y; k[8] = w1.z; k[9] = w1.w;

    // query tokens (uniform-address LDG -> broadcast)
    const int q0 = xb[T_SZ - 1];
    const int q1 = xb[T_SZ - 2];
    const int q2 = xb[T_SZ - 3];

    const float p00 = params[0], p01 = params[1], p02 = params[2];
    const float p10 = params[3], p11 = params[4], p12 = params[5];
    const float p20 = params[6], p21 = params[7], p22 = params[8];

    // score(t) = sum_{i,j} p[i][j] * [q_i == toks[t-j]]
    float e[TPT];
    float corr = 0.0f;
    #pragma unroll
    for (int i = 0; i < TPT; i++) {
        const int k0 = k[i + 2];   // toks[t]
        const int k1 = k[i + 1];   // toks[t-1]
        const int k2 = k[i];       // toks[t-2]
        float s;
        s  = (q0 == k0) ? p00 : 0.0f;
        s += (q0 == k1) ? p01 : 0.0f;
        s += (q0 == k2) ? p02 : 0.0f;
        s += (q1 == k0) ? p10 : 0.0f;
        s += (q1 == k1) ? p11 : 0.0f;
        s += (q1 == k2) ? p12 : 0.0f;
        s += (q2 == k0) ? p20 : 0.0f;
        s += (q2 == k1) ? p21 : 0.0f;
        s += (q2 == k2) ? p22 : 0.0f;

        const bool masked = (i == TPT - 1) && (tid == NT - 1);  // t == T-1
        const float ev = masked ? 0.0f : __expf(s);
        e[i] = ev;
        if (s != 0.0f && !masked) corr += ev - 1.0f;
    }
    if (corr != 0.0f) atomicAdd(&zcorr, corr);

    __syncthreads();   // BAR 1: zcorr + vslice zero visible

    const float inv = __fdividef(1.0f, 2047.0f + zcorr);

    // ---- scatter: only tokens in this CTA's 512-entry slice (~128/CTA) ----
    #pragma unroll
    for (int i = 0; i < TPT; i++) {
        const int tok = k[i + 2];
        if ((tok >> 9) == slice)
            atomicAdd(&vslice[tok & (SLICE - 1)], e[i] * inv);
    }

    __syncthreads();   // BAR 2

    // ---- store this CTA's 2 KB slice (coalesced, 2 floats per thread) ----
    float* ob = out + b * VOCAB + slice * SLICE;
    ob[tid]      = vslice[tid];
    ob[tid + NT] = vslice[tid + NT];
}

extern "C" void kernel_launch(void* const* d_in, const int* in_sizes, int n_in,
                              void* d_out, int out_size)
{
    const int*   x      = (const int*)d_in[0];     // (8, 2048) int32
    const float* params = (const float*)d_in[1];   // (3, 3) float32
    float*       out    = (float*)d_out;           // (8, 8192) float32

    (void)in_sizes; (void)n_in; (void)out_size;
    constrained_attn_kernel<<<B_SZ * SPLIT, NT>>>(x, params, out);
}